// round 14
// baseline (speedup 1.0000x reference)
#include <cuda_runtime.h>
#include <cuda_fp16.h>
#include <math.h>

#define NB 1024
#define NSTEPS 10
typedef unsigned int u32;

#define STR   272
#define WHALF 34816
#define WBYTES 69632
#define S_A0  0
#define S_A1  34816
#define S_W   69632
#define S_G   208896
#define S_TOT 212992

__device__ float g_y[NB*16], g_ys[NB*16], g_V[NB*256];
__device__ __align__(16) __half g_Wt[5][34816];   // hidden layers: hi[128][136], lo[128][136]
__device__ __align__(16) __half g_W0c[2][5120];   // L0 compact: 128 rows x 40 halves (64B payload, 80B stride)
__device__ __align__(16) __half g_W4c[2][2176];   // L4 compact: 16 rows x 136 halves (272B stride)

__global__ void prep(const float* __restrict__ W0, const float* __restrict__ W1,
                     const float* __restrict__ W2, const float* __restrict__ W3,
                     const float* __restrict__ W4)
{
  int i = blockIdx.x*256 + threadIdx.x;
  if (i < 3*128*136){
    int l = i/(128*136), r = i%(128*136), n = r/136, k = r%136;
    const float* W = (l==0)?W1:(l==1)?W2:W3;
    float w = (k<128)? W[k*128+n] : 0.f;
    __half h = __float2half_rn(w);
    g_Wt[l+1][n*136+k] = h;
    g_Wt[l+1][17408 + n*136+k] = __float2half_rn(w - __half2float(h));
  }
  if (i < 128*32){           // L0 compact
    int n = i>>5, k = i&31;
    float w = (k<17)? W0[k*128+n] : 0.f;
    __half h = __float2half_rn(w);
    g_W0c[0][n*40+k] = h;
    g_W0c[1][n*40+k] = __float2half_rn(w - __half2float(h));
  }
  if (i < 16*136){           // L4 compact
    int n = i/136, k = i%136;
    float w = (k<128)? W4[k*16+n] : 0.f;
    __half h = __float2half_rn(w);
    g_W4c[0][n*136+k] = h;
    g_W4c[1][n*136+k] = __float2half_rn(w - __half2float(h));
  }
}

__device__ __forceinline__ u32 s2u(const void* p){ u32 a;
  asm("{.reg .u64 t; cvta.to.shared.u64 t,%1; cvt.u32.u64 %0,t;}":"=r"(a):"l"(p)); return a; }
__device__ __forceinline__ void ldm4(u32 a, u32 r[4]){
  asm volatile("ldmatrix.sync.aligned.m8n8.x4.shared.b16 {%0,%1,%2,%3},[%4];"
    :"=r"(r[0]),"=r"(r[1]),"=r"(r[2]),"=r"(r[3]):"r"(a)); }
__device__ __forceinline__ void mmaop(float d[4], const u32 a[4], u32 b0, u32 b1){
  asm volatile("mma.sync.aligned.m16n8k16.row.col.f32.f16.f16.f32 "
    "{%0,%1,%2,%3},{%4,%5,%6,%7},{%8,%9},{%0,%1,%2,%3};"
    :"+f"(d[0]),"+f"(d[1]),"+f"(d[2]),"+f"(d[3])
    :"r"(a[0]),"r"(a[1]),"r"(a[2]),"r"(a[3]),"r"(b0),"r"(b1)); }
#define CPASYNC(dst,src) asm volatile("cp.async.cg.shared.global [%0],[%1],16;"::"r"(dst),"l"(src):"memory")
#define CPCOMMIT() asm volatile("cp.async.commit_group;":::"memory")
#define CPWAIT()   asm volatile("cp.async.wait_group 0;":::"memory")

__device__ __forceinline__ void sts2(char* sm, u32 o, float a, float b){
  __half ha=__float2half_rn(a), hb=__float2half_rn(b);
  __half la=__float2half_rn(a-__half2float(ha)), lb=__float2half_rn(b-__half2float(hb));
  *(__half2*)(sm + S_A0 + o) = __halves2half2(ha,hb);
  *(__half2*)(sm + S_A1 + o) = __halves2half2(la,lb);
}

// tanh via ex2/rcp approx: abs err ~1e-7, saturates correctly
__device__ __forceinline__ float ftanh(float x){
  float t; asm("ex2.approx.f32 %0, %1;" : "=f"(t) : "f"(x*2.8853900817779268f));
  float r; asm("rcp.approx.f32 %0, %1;" : "=f"(r) : "f"(t+1.f));
  return fmaf(-2.f, r, 1.f);
}

__global__ __launch_bounds__(256,1)
void flow(const float* __restrict__ x,  const float* __restrict__ xs,
          const float* __restrict__ b0, const float* __restrict__ b1,
          const float* __restrict__ b2, const float* __restrict__ b3,
          const float* __restrict__ b4)
{
  extern __shared__ char sm[];
  const u32 sb = s2u(sm);
  const int tid = threadIdx.x, w = tid>>5, l = tid&31;
  const int P0 = blockIdx.x*7;                    // 147 CTAs x 7 points
  const int mb = w>>1, nb = w&1;                  // mb3 warps = w6,w7
  const int lr = l>>2, lc2 = (l&3)*2;

  const u32 offA  = (u32)(l&15)*STR + (u32)(l>>4)*16;
  const u32 offB  = ((u32)(l&7) + ((u32)(l>>4)&1)*8)*STR + (((u32)l>>3)&1)*16;
  const u32 offB0 = ((u32)(l&7) + ((u32)(l>>4)&1)*8)*80u + (((u32)l>>3)&1)*16;

  // state: w<7 -> tangent of point P0+w ; w==7 -> 16 trajectories (J rows 112-119, star 120-127)
  float v[2][4], uu[2][4], usum[2][4], zz[2][4], kst[2][4], ksum[2][4];
  #pragma unroll
  for (int nf=0; nf<2; ++nf)
    #pragma unroll
    for (int r=0; r<4; ++r){
      int dir = lr + ((r>=2)?8:0), comp = nf*8 + lc2 + (r&1);
      v[nf][r] = (dir==comp)?1.f:0.f; uu[nf][r]=0.f;
      zz[nf][r]=0.f; kst[nf][r]=0.f;
    }
  const bool pval = (lr<7) && (P0+lr < NB);
  if (w==7 && pval){
    #pragma unroll
    for (int nf=0; nf<2; ++nf){
      int n = nf*8 + lc2;
      zz[nf][0] = x [(P0+lr)*16 + n];   zz[nf][1] = x [(P0+lr)*16 + n+1];
      zz[nf][2] = xs[(P0+lr)*16 + n];   zz[nf][3] = xs[(P0+lr)*16 + n+1];
    }
  }

  { // initial W prefetch (layer 0 compact -> buf 0)
    const char* src = (const char*)g_W0c;
    u32 dst = sb + S_W;
    for (int i=tid; i<1280; i+=256) CPASYNC(dst + i*16, src + i*16);
    CPCOMMIT();
  }
  int wp = 0;
  const float dt = 1.f/NSTEPS, f6 = dt/6.f;

  for (int step=0; step<NSTEPS; ++step){
    const float t0 = step*dt;
    #pragma unroll
    for (int nf=0; nf<2; ++nf)
      #pragma unroll
      for (int r=0; r<4; ++r){ usum[nf][r]=0.f; ksum[nf][r]=0.f; }

    for (int s=0; s<4; ++s){
      const float cs = (s==0)?0.f:((s==3)?dt:0.5f*dt);
      const float ts = t0+cs, wgt = (s==0||s==3)?1.f:2.f;

      // ---- stage inputs ----
      if (w<7){
        #pragma unroll
        for (int nf=0; nf<2; ++nf){
          int n = nf*8 + lc2;
          sts2(sm, (u32)((w*16+lr  )*STR + n*2), v[nf][0]+cs*uu[nf][0], v[nf][1]+cs*uu[nf][1]);
          sts2(sm, (u32)((w*16+lr+8)*STR + n*2), v[nf][2]+cs*uu[nf][2], v[nf][3]+cs*uu[nf][3]);
        }
      } else {
        #pragma unroll
        for (int nf=0; nf<2; ++nf){
          int n = nf*8 + lc2;
          sts2(sm, (u32)((112+lr)*STR + n*2), zz[nf][0]+cs*kst[nf][0], zz[nf][1]+cs*kst[nf][1]);
          sts2(sm, (u32)((120+lr)*STR + n*2), zz[nf][2]+cs*kst[nf][2], zz[nf][3]+cs*kst[nf][3]);
        }
        if (l<16){
          int row = 112+l; uint4 z4 = make_uint4(0,0,0,0);
          *(uint4*)(sm + S_A0 + row*STR + 32) = z4; *(uint4*)(sm + S_A0 + row*STR + 48) = z4;
          *(uint4*)(sm + S_A1 + row*STR + 32) = z4; *(uint4*)(sm + S_A1 + row*STR + 48) = z4;
        }
        __syncwarp();
        if (l<16){
          int row = 112+l;
          __half th = __float2half_rn(ts);
          *(__half*)(sm + S_A0 + row*STR + 32) = th;
          *(__half*)(sm + S_A1 + row*STR + 32) = __float2half_rn(ts - __half2float(th));
        }
      }

      for (int ly=0; ly<5; ++ly){
        CPWAIT();
        __syncthreads();   // W[ly] ready; A writes visible
        if (!(step==NSTEPS-1 && s==3 && ly==4)){
          const int nxt = (ly+1)%5;
          const char* src; int n4;
          if (nxt==0){ src = (const char*)g_W0c; n4 = 1280; }
          else if (nxt==4){ src = (const char*)g_W4c; n4 = 544; }
          else { src = (const char*)g_Wt[nxt]; n4 = 4352; }
          u32 dst = sb + S_W + (u32)(wp^1)*WBYTES;
          for (int i=tid; i<n4; i+=256) CPASYNC(dst + i*16, src + i*16);
          CPCOMMIT();
        }
        const u32 wbh = sb + S_W + (u32)wp*WBYTES;

        if (ly<4){
          const bool isL0 = (ly==0);
          const u32 rstr = isL0 ? 80u : (u32)STR;
          const u32 ob   = isL0 ? offB0 : offB;
          const u32 wbl  = wbh + (isL0 ? 10240u : (u32)WHALF);

          float Dt[2][8][4];
          #pragma unroll
          for (int mf=0; mf<2; ++mf)
            #pragma unroll
            for (int nf=0; nf<8; ++nf)
              #pragma unroll
              for (int r=0; r<4; ++r) Dt[mf][nf][r]=0.f;

          const int KCfull = ly ? 8 : ((mb==3)?2:1);
          #pragma unroll 2
          for (int kc=0; kc<KCfull; ++kc){
            const u32 kb = (u32)kc*32;
            const bool doM0 = (ly>0) || (kc==0);   // L0 kc=1: primal rows only
            u32 Ah[2][4], Al[2][4];
            if (doM0){
              ldm4(sb + S_A0 + (u32)(mb*32)*STR + kb + offA, Ah[0]);
              ldm4(sb + S_A1 + (u32)(mb*32)*STR + kb + offA, Al[0]);
            }
            ldm4(sb + S_A0 + (u32)(mb*32+16)*STR + kb + offA, Ah[1]);
            ldm4(sb + S_A1 + (u32)(mb*32+16)*STR + kb + offA, Al[1]);
            #pragma unroll
            for (int g=0; g<4; ++g){
              u32 Bh[4], Bl[4];
              ldm4(wbh + (u32)(nb*64+g*16)*rstr + kb + ob, Bh);
              ldm4(wbl + (u32)(nb*64+g*16)*rstr + kb + ob, Bl);
              if (doM0){
                mmaop(Dt[0][g*2  ], Ah[0], Bh[0],Bh[1]);
                mmaop(Dt[0][g*2  ], Al[0], Bh[0],Bh[1]);
                mmaop(Dt[0][g*2  ], Ah[0], Bl[0],Bl[1]);
                mmaop(Dt[0][g*2+1], Ah[0], Bh[2],Bh[3]);
                mmaop(Dt[0][g*2+1], Al[0], Bh[2],Bh[3]);
                mmaop(Dt[0][g*2+1], Ah[0], Bl[2],Bl[3]);
              }
              mmaop(Dt[1][g*2  ], Ah[1], Bh[0],Bh[1]);
              mmaop(Dt[1][g*2  ], Al[1], Bh[0],Bh[1]);
              mmaop(Dt[1][g*2  ], Ah[1], Bl[0],Bl[1]);
              mmaop(Dt[1][g*2+1], Ah[1], Bh[2],Bh[3]);
              mmaop(Dt[1][g*2+1], Al[1], Bh[2],Bh[3]);
              mmaop(Dt[1][g*2+1], Ah[1], Bl[2],Bl[3]);
            }
          }
          __syncthreads();   // all mma reads of A done
          // phase 1: primal bias+tanh (mb==3 warps: mf=1 rows are trajectories)
          const float* bias = (ly==0)?b0:(ly==1)?b1:(ly==2)?b2:b3;
          if (mb==3){
            #pragma unroll
            for (int nf=0; nf<8; ++nf){
              int n = nb*64 + nf*8 + lc2;
              float bx = bias[n], by = bias[n+1];
              float hJ0=ftanh(Dt[1][nf][0]+bx), hJ1=ftanh(Dt[1][nf][1]+by);
              float hS0=ftanh(Dt[1][nf][2]+bx), hS1=ftanh(Dt[1][nf][3]+by);
              sts2(sm, (u32)((112+lr)*STR + n*2), hJ0, hJ1);
              sts2(sm, (u32)((120+lr)*STR + n*2), hS0, hS1);
              *(float2*)(sm + S_G + lr*512 + n*4) = make_float2(1.f-hJ0*hJ0, 1.f-hJ1*hJ1);
            }
          }
          __syncthreads();
          // phase 2: tangent scale-by-g -> next A (mb3 warps: mf=0 only)
          #pragma unroll
          for (int mf=0; mf<2; ++mf){
            if (mb==3 && mf==1) break;
            int p = mb*2 + mf;
            #pragma unroll
            for (int nf=0; nf<8; ++nf){
              int n = nb*64 + nf*8 + lc2;
              float2 gv = *(float2*)(sm + S_G + p*512 + n*4);
              int r0 = mb*32 + mf*16 + lr;
              sts2(sm, (u32)(r0*STR + n*2),     Dt[mf][nf][0]*gv.x, Dt[mf][nf][1]*gv.y);
              sts2(sm, (u32)((r0+8)*STR + n*2), Dt[mf][nf][2]*gv.x, Dt[mf][nf][3]*gv.y);
            }
          }
        } else {
          // L4 (compact tile: 16 rows, lo at +4352): warps 0-6 tangent, warp 7 primal
          const u32 wbl4 = wbh + 4352u;
          float D4[2][4];
          #pragma unroll
          for (int nf=0; nf<2; ++nf)
            #pragma unroll
            for (int r=0; r<4; ++r) D4[nf][r]=0.f;
          const u32 arow = (w<7) ? (u32)(w*16) : 112u;
          #pragma unroll 2
          for (int kc=0; kc<8; ++kc){
            const u32 kb = (u32)kc*32;
            u32 Ah[4], Al[4], Bh[4], Bl[4];
            ldm4(sb + S_A0 + arow*STR + kb + offA, Ah);
            ldm4(sb + S_A1 + arow*STR + kb + offA, Al);
            ldm4(wbh  + kb + offB, Bh);
            ldm4(wbl4 + kb + offB, Bl);
            mmaop(D4[0],Ah,Bh[0],Bh[1]); mmaop(D4[0],Al,Bh[0],Bh[1]); mmaop(D4[0],Ah,Bl[0],Bl[1]);
            mmaop(D4[1],Ah,Bh[2],Bh[3]); mmaop(D4[1],Al,Bh[2],Bh[3]); mmaop(D4[1],Ah,Bl[2],Bl[3]);
          }
          __syncthreads();   // A reads done before next stage-input writes
          if (w<7){
            #pragma unroll
            for (int nf=0; nf<2; ++nf)
              #pragma unroll
              for (int r=0; r<4; ++r){ uu[nf][r]=D4[nf][r]; usum[nf][r]+=wgt*D4[nf][r]; }
          } else {
            #pragma unroll
            for (int nf=0; nf<2; ++nf){
              int n = nf*8 + lc2;
              kst[nf][0]=D4[nf][0]+b4[n]; kst[nf][1]=D4[nf][1]+b4[n+1];
              kst[nf][2]=D4[nf][2]+b4[n]; kst[nf][3]=D4[nf][3]+b4[n+1];
              #pragma unroll
              for (int r=0; r<4; ++r) ksum[nf][r]+=wgt*kst[nf][r];
            }
          }
        }
        wp ^= 1;
      } // layers
    } // stages

    #pragma unroll
    for (int nf=0; nf<2; ++nf)
      #pragma unroll
      for (int r=0; r<4; ++r){ v[nf][r] += f6*usum[nf][r]; zz[nf][r] += f6*ksum[nf][r]; }
  } // steps

  // outputs
  if (w<7 && (P0+w) < NB){
    #pragma unroll
    for (int nf=0; nf<2; ++nf)
      #pragma unroll
      for (int r=0; r<4; ++r){
        int dir = lr + ((r>=2)?8:0), comp = nf*8 + lc2 + (r&1);
        g_V[(P0+w)*256 + dir*16 + comp] = v[nf][r];
      }
  }
  if (w==7 && pval){
    #pragma unroll
    for (int nf=0; nf<2; ++nf){
      int n = nf*8 + lc2;
      g_y [(P0+lr)*16 + n  ] = zz[nf][0];
      g_y [(P0+lr)*16 + n+1] = zz[nf][1];
      g_ys[(P0+lr)*16 + n  ] = zz[nf][2];
      g_ys[(P0+lr)*16 + n+1] = zz[nf][3];
    }
  }
}

// ============== finalize: one warp per point, lane j owns row j ==============
__global__ __launch_bounds__(256)
void finalize2(float* __restrict__ out)
{
  __shared__ float tp[8][17*16];
  const int wid = threadIdx.x >> 5, l = threadIdx.x & 31, j = l & 15;
  const int p = blockIdx.x*8 + wid;
  const unsigned FULL = 0xffffffffu;

  float R[16];
  {
    const float4* Vp = (const float4*)(g_V + p*256 + j*16);
    #pragma unroll
    for (int q=0; q<4; ++q){ float4 t = Vp[q];
      R[q*4]=t.x; R[q*4+1]=t.y; R[q*4+2]=t.z; R[q*4+3]=t.w; }
  }
  float gph[16], n2 = 0.f;
  #pragma unroll
  for (int i=0;i<16;++i){ float d = g_y[p*16+i]-g_ys[p*16+i]; gph[i]=d; n2+=d*d; }
  float inv = 1.f/(sqrtf(n2)+1e-8f);
  #pragma unroll
  for (int i=0;i<16;++i) gph[i]*=inv;
  float gx = 0.f;
  #pragma unroll
  for (int i=0;i<16;++i) gx += R[i]*gph[i];

  float A[16];
  #pragma unroll
  for (int k=0;k<16;++k){
    float s = 0.f;
    #pragma unroll
    for (int i=0;i<16;++i) s += R[i]*__shfl_sync(FULL, R[i], k);
    A[k] = s + ((k==j)?1e-6f:0.f);
  }

  #pragma unroll
  for (int k=0;k<16;++k){
    float akk = __shfl_sync(FULL, A[k], k);
    float dk  = sqrtf(fmaxf(akk, 1e-30f));
    float idk = 1.f/dk;
    float cand = A[k]*idk;
    A[k] = (j>=k)? cand : A[k];
    float mylk = (j>k)? A[k] : 0.f;
    #pragma unroll
    for (int i=k+1;i<16;++i){
      float lik = __shfl_sync(FULL, A[k], i);
      A[i] -= mylk*lik;
    }
  }

  float acc = 0.f, yvj = 0.f;
  #pragma unroll
  for (int i=0;i<16;++i){
    float num = __shfl_sync(FULL, gx - acc, i);
    float di  = __shfl_sync(FULL, A[i], i);
    float yvi = num/di;
    if (j==i) yvj = yvi;
    acc += ((j>i)? A[i] : 0.f)*yvi;
  }

  if (l < 16){
    #pragma unroll
    for (int i=0;i<16;++i) tp[wid][j*17 + i] = A[i];
  }
  __syncwarp();
  float U[16];
  #pragma unroll
  for (int i=0;i<16;++i) U[i] = tp[wid][i*17 + j];

  float acc2 = 0.f, sj = 0.f;
  #pragma unroll
  for (int i=15;i>=0;--i){
    float num = __shfl_sync(FULL, yvj - acc2, i);
    float di  = __shfl_sync(FULL, U[i], i);
    float si  = num/di;
    if (j==i) sj = si;
    acc2 += ((j<i)? U[i] : 0.f)*si;
  }
  if (l < 16) out[p*16 + j] = -sj;
}

extern "C" void kernel_launch(void* const* d_in, const int* in_sizes, int n_in,
                              void* d_out, int out_size)
{
  const float* x  = (const float*)d_in[0];
  const float* xs = (const float*)d_in[1];
  const float* W0 = (const float*)d_in[2];
  const float* b0 = (const float*)d_in[3];
  const float* W1 = (const float*)d_in[4];
  const float* b1 = (const float*)d_in[5];
  const float* W2 = (const float*)d_in[6];
  const float* b2 = (const float*)d_in[7];
  const float* W3 = (const float*)d_in[8];
  const float* b3 = (const float*)d_in[9];
  const float* W4 = (const float*)d_in[10];
  const float* b4 = (const float*)d_in[11];
  float* out = (float*)d_out;

  prep<<<204,256>>>(W0,W1,W2,W3,W4);
  cudaFuncSetAttribute(flow, cudaFuncAttributeMaxDynamicSharedMemorySize, S_TOT);
  flow<<<147,256,S_TOT>>>(x,xs,b0,b1,b2,b3,b4);
  finalize2<<<128,256>>>(out);
}

// round 15
// speedup vs baseline: 1.0316x; 1.0316x over previous
#include <cuda_runtime.h>
#include <cuda_fp16.h>
#include <math.h>

#define NB 1024
#define NSTEPS 10
typedef unsigned int u32;

#define STR   272
#define WHALF 34816
#define WBYTES 69632
#define S_A0  0
#define S_A1  34816
#define S_W   69632
#define S_G   208896
#define S_TOT 212992

__device__ float g_y[NB*16], g_ys[NB*16], g_V[NB*256];
__device__ __align__(16) __half g_Wt[5][34816];   // hidden layers 1-3: hi[128][136], lo[128][136]
__device__ __align__(16) __half g_W0c[2][5120];   // L0 compact: 128 rows x 40 halves (80B stride)
__device__ __align__(16) __half g_W4c[2][2176];   // L4 compact: 16 rows x 136 halves (272B stride)

__global__ void prep(const float* __restrict__ W0, const float* __restrict__ W1,
                     const float* __restrict__ W2, const float* __restrict__ W3,
                     const float* __restrict__ W4)
{
  int i = blockIdx.x*256 + threadIdx.x;
  if (i < 3*128*136){
    int l = i/(128*136), r = i%(128*136), n = r/136, k = r%136;
    const float* W = (l==0)?W1:(l==1)?W2:W3;
    float w = (k<128)? W[k*128+n] : 0.f;
    __half h = __float2half_rn(w);
    g_Wt[l+1][n*136+k] = h;
    g_Wt[l+1][17408 + n*136+k] = __float2half_rn(w - __half2float(h));
  }
  if (i < 128*32){           // L0 compact
    int n = i>>5, k = i&31;
    float w = (k<17)? W0[k*128+n] : 0.f;
    __half h = __float2half_rn(w);
    g_W0c[0][n*40+k] = h;
    g_W0c[1][n*40+k] = __float2half_rn(w - __half2float(h));
  }
  if (i < 16*136){           // L4 compact
    int n = i/136, k = i%136;
    float w = (k<128)? W4[k*16+n] : 0.f;
    __half h = __float2half_rn(w);
    g_W4c[0][n*136+k] = h;
    g_W4c[1][n*136+k] = __float2half_rn(w - __half2float(h));
  }
}

__device__ __forceinline__ u32 s2u(const void* p){ u32 a;
  asm("{.reg .u64 t; cvta.to.shared.u64 t,%1; cvt.u32.u64 %0,t;}":"=r"(a):"l"(p)); return a; }
__device__ __forceinline__ void ldm4(u32 a, u32 r[4]){
  asm volatile("ldmatrix.sync.aligned.m8n8.x4.shared.b16 {%0,%1,%2,%3},[%4];"
    :"=r"(r[0]),"=r"(r[1]),"=r"(r[2]),"=r"(r[3]):"r"(a)); }
__device__ __forceinline__ void mmaop(float d[4], const u32 a[4], u32 b0, u32 b1){
  asm volatile("mma.sync.aligned.m16n8k16.row.col.f32.f16.f16.f32 "
    "{%0,%1,%2,%3},{%4,%5,%6,%7},{%8,%9},{%0,%1,%2,%3};"
    :"+f"(d[0]),"+f"(d[1]),"+f"(d[2]),"+f"(d[3])
    :"r"(a[0]),"r"(a[1]),"r"(a[2]),"r"(a[3]),"r"(b0),"r"(b1)); }
#define CPASYNC(dst,src) asm volatile("cp.async.cg.shared.global [%0],[%1],16;"::"r"(dst),"l"(src):"memory")
#define CPCOMMIT() asm volatile("cp.async.commit_group;":::"memory")
#define CPWAIT()   asm volatile("cp.async.wait_group 0;":::"memory")

__device__ __forceinline__ void sts2(char* sm, u32 o, float a, float b){
  __half ha=__float2half_rn(a), hb=__float2half_rn(b);
  __half la=__float2half_rn(a-__half2float(ha)), lb=__float2half_rn(b-__half2float(hb));
  *(__half2*)(sm + S_A0 + o) = __halves2half2(ha,hb);
  *(__half2*)(sm + S_A1 + o) = __halves2half2(la,lb);
}

// tanh via ex2/rcp approx: abs err ~1e-7, saturates correctly
__device__ __forceinline__ float ftanh(float x){
  float t; asm("ex2.approx.f32 %0, %1;" : "=f"(t) : "f"(x*2.8853900817779268f));
  float r; asm("rcp.approx.f32 %0, %1;" : "=f"(r) : "f"(t+1.f));
  return fmaf(-2.f, r, 1.f);
}

// inner g-block: 8 ldm4 (B hi/lo) + up to 12 mma
#define GBLOCK(WBH, WBL, RSTR, OB, DOM0) \
  _Pragma("unroll") \
  for (int g=0; g<4; ++g){ \
    u32 Bh[4], Bl[4]; \
    ldm4((WBH) + (u32)((nb*64+g*16)*(RSTR)) + kb + (OB), Bh); \
    ldm4((WBL) + (u32)((nb*64+g*16)*(RSTR)) + kb + (OB), Bl); \
    if (DOM0){ \
      mmaop(Dt[0][g*2  ], Ah[0], Bh[0],Bh[1]); \
      mmaop(Dt[0][g*2  ], Al[0], Bh[0],Bh[1]); \
      mmaop(Dt[0][g*2  ], Ah[0], Bl[0],Bl[1]); \
      mmaop(Dt[0][g*2+1], Ah[0], Bh[2],Bh[3]); \
      mmaop(Dt[0][g*2+1], Al[0], Bh[2],Bh[3]); \
      mmaop(Dt[0][g*2+1], Ah[0], Bl[2],Bl[3]); \
    } \
    mmaop(Dt[1][g*2  ], Ah[1], Bh[0],Bh[1]); \
    mmaop(Dt[1][g*2  ], Al[1], Bh[0],Bh[1]); \
    mmaop(Dt[1][g*2  ], Ah[1], Bl[0],Bl[1]); \
    mmaop(Dt[1][g*2+1], Ah[1], Bh[2],Bh[3]); \
    mmaop(Dt[1][g*2+1], Al[1], Bh[2],Bh[3]); \
    mmaop(Dt[1][g*2+1], Ah[1], Bl[2],Bl[3]); \
  }

__global__ __launch_bounds__(256,1)
void flow(const float* __restrict__ x,  const float* __restrict__ xs,
          const float* __restrict__ b0, const float* __restrict__ b1,
          const float* __restrict__ b2, const float* __restrict__ b3,
          const float* __restrict__ b4)
{
  extern __shared__ char sm[];
  const u32 sb = s2u(sm);
  const int tid = threadIdx.x, w = tid>>5, l = tid&31;
  const int P0 = blockIdx.x*7;                    // 147 CTAs x 7 points
  const int mb = w>>1, nb = w&1;                  // mb3 warps = w6,w7
  const int lr = l>>2, lc2 = (l&3)*2;

  const u32 offA  = (u32)(l&15)*STR + (u32)(l>>4)*16;
  const u32 offB  = ((u32)(l&7) + ((u32)(l>>4)&1)*8)*STR + (((u32)l>>3)&1)*16;
  const u32 offB0 = ((u32)(l&7) + ((u32)(l>>4)&1)*8)*80u + (((u32)l>>3)&1)*16;

  // state: w<7 -> tangent of point P0+w ; w==7 -> 16 trajectories (J rows 112-119, star 120-127)
  float v[2][4], uu[2][4], usum[2][4], zz[2][4], kst[2][4], ksum[2][4];
  #pragma unroll
  for (int nf=0; nf<2; ++nf)
    #pragma unroll
    for (int r=0; r<4; ++r){
      int dir = lr + ((r>=2)?8:0), comp = nf*8 + lc2 + (r&1);
      v[nf][r] = (dir==comp)?1.f:0.f; uu[nf][r]=0.f;
      zz[nf][r]=0.f; kst[nf][r]=0.f;
    }
  const bool pval = (lr<7) && (P0+lr < NB);
  if (w==7 && pval){
    #pragma unroll
    for (int nf=0; nf<2; ++nf){
      int n = nf*8 + lc2;
      zz[nf][0] = x [(P0+lr)*16 + n];   zz[nf][1] = x [(P0+lr)*16 + n+1];
      zz[nf][2] = xs[(P0+lr)*16 + n];   zz[nf][3] = xs[(P0+lr)*16 + n+1];
    }
  }

  { // initial W prefetch (layer 0 compact -> buf 0)
    const char* src = (const char*)g_W0c;
    u32 dst = sb + S_W;
    for (int i=tid; i<1280; i+=256) CPASYNC(dst + i*16, src + i*16);
    CPCOMMIT();
  }
  int wp = 0;
  const float dt = 1.f/NSTEPS, f6 = dt/6.f;

  for (int step=0; step<NSTEPS; ++step){
    const float t0 = step*dt;
    #pragma unroll
    for (int nf=0; nf<2; ++nf)
      #pragma unroll
      for (int r=0; r<4; ++r){ usum[nf][r]=0.f; ksum[nf][r]=0.f; }

    for (int s=0; s<4; ++s){
      const float cs = (s==0)?0.f:((s==3)?dt:0.5f*dt);
      const float ts = t0+cs, wgt = (s==0||s==3)?1.f:2.f;

      // ---- stage inputs ----
      if (w<7){
        #pragma unroll
        for (int nf=0; nf<2; ++nf){
          int n = nf*8 + lc2;
          sts2(sm, (u32)((w*16+lr  )*STR + n*2), v[nf][0]+cs*uu[nf][0], v[nf][1]+cs*uu[nf][1]);
          sts2(sm, (u32)((w*16+lr+8)*STR + n*2), v[nf][2]+cs*uu[nf][2], v[nf][3]+cs*uu[nf][3]);
        }
      } else {
        #pragma unroll
        for (int nf=0; nf<2; ++nf){
          int n = nf*8 + lc2;
          sts2(sm, (u32)((112+lr)*STR + n*2), zz[nf][0]+cs*kst[nf][0], zz[nf][1]+cs*kst[nf][1]);
          sts2(sm, (u32)((120+lr)*STR + n*2), zz[nf][2]+cs*kst[nf][2], zz[nf][3]+cs*kst[nf][3]);
        }
        if (l<16){
          int row = 112+l; uint4 z4 = make_uint4(0,0,0,0);
          *(uint4*)(sm + S_A0 + row*STR + 32) = z4; *(uint4*)(sm + S_A0 + row*STR + 48) = z4;
          *(uint4*)(sm + S_A1 + row*STR + 32) = z4; *(uint4*)(sm + S_A1 + row*STR + 48) = z4;
        }
        __syncwarp();
        if (l<16){
          int row = 112+l;
          __half th = __float2half_rn(ts);
          *(__half*)(sm + S_A0 + row*STR + 32) = th;
          *(__half*)(sm + S_A1 + row*STR + 32) = __float2half_rn(ts - __half2float(th));
        }
      }

      for (int ly=0; ly<5; ++ly){
        CPWAIT();
        __syncthreads();   // W[ly] ready; A writes visible
        if (!(step==NSTEPS-1 && s==3 && ly==4)){
          const int nxt = (ly+1)%5;
          const char* src; int n4;
          if (nxt==0){ src = (const char*)g_W0c; n4 = 1280; }
          else if (nxt==4){ src = (const char*)g_W4c; n4 = 544; }
          else { src = (const char*)g_Wt[nxt]; n4 = 4352; }
          u32 dst = sb + S_W + (u32)(wp^1)*WBYTES;
          for (int i=tid; i<n4; i+=256) CPASYNC(dst + i*16, src + i*16);
          CPCOMMIT();
        }
        const u32 wbh = sb + S_W + (u32)wp*WBYTES;

        if (ly<4){
          float Dt[2][8][4];
          #pragma unroll
          for (int mf=0; mf<2; ++mf)
            #pragma unroll
            for (int nf=0; nf<8; ++nf)
              #pragma unroll
              for (int r=0; r<4; ++r) Dt[mf][nf][r]=0.f;

          if (ly==0){
            // L0: compact B tile, constant stride 80, lo at +10240
            const u32 wbl = wbh + 10240u;
            const int KCfull = (mb==3)?2:1;
            #pragma unroll 2
            for (int kc=0; kc<KCfull; ++kc){
              const u32 kb = (u32)kc*32;
              const bool doM0 = (kc==0);
              u32 Ah[2][4], Al[2][4];
              if (doM0){
                ldm4(sb + S_A0 + (u32)(mb*32)*STR + kb + offA, Ah[0]);
                ldm4(sb + S_A1 + (u32)(mb*32)*STR + kb + offA, Al[0]);
              }
              ldm4(sb + S_A0 + (u32)(mb*32+16)*STR + kb + offA, Ah[1]);
              ldm4(sb + S_A1 + (u32)(mb*32+16)*STR + kb + offA, Al[1]);
              GBLOCK(wbh, wbl, 80, offB0, doM0)
            }
          } else {
            // layers 1-3: full B tile, constant stride STR, lo at +WHALF
            const u32 wbl = wbh + WHALF;
            #pragma unroll 2
            for (int kc=0; kc<8; ++kc){
              const u32 kb = (u32)kc*32;
              u32 Ah[2][4], Al[2][4];
              ldm4(sb + S_A0 + (u32)(mb*32)*STR + kb + offA, Ah[0]);
              ldm4(sb + S_A1 + (u32)(mb*32)*STR + kb + offA, Al[0]);
              ldm4(sb + S_A0 + (u32)(mb*32+16)*STR + kb + offA, Ah[1]);
              ldm4(sb + S_A1 + (u32)(mb*32+16)*STR + kb + offA, Al[1]);
              GBLOCK(wbh, wbl, STR, offB, true)
            }
          }
          __syncthreads();   // all mma reads of A done
          // phase 1: primal bias+tanh (mb==3 warps: mf=1 rows are trajectories)
          const float* bias = (ly==0)?b0:(ly==1)?b1:(ly==2)?b2:b3;
          if (mb==3){
            #pragma unroll
            for (int nf=0; nf<8; ++nf){
              int n = nb*64 + nf*8 + lc2;
              float bx = bias[n], by = bias[n+1];
              float hJ0=ftanh(Dt[1][nf][0]+bx), hJ1=ftanh(Dt[1][nf][1]+by);
              float hS0=ftanh(Dt[1][nf][2]+bx), hS1=ftanh(Dt[1][nf][3]+by);
              sts2(sm, (u32)((112+lr)*STR + n*2), hJ0, hJ1);
              sts2(sm, (u32)((120+lr)*STR + n*2), hS0, hS1);
              *(float2*)(sm + S_G + lr*512 + n*4) = make_float2(1.f-hJ0*hJ0, 1.f-hJ1*hJ1);
            }
          }
          __syncthreads();
          // phase 2: tangent scale-by-g -> next A (mb3 warps: mf=0 only)
          #pragma unroll
          for (int mf=0; mf<2; ++mf){
            if (mb==3 && mf==1) break;
            int p = mb*2 + mf;
            #pragma unroll
            for (int nf=0; nf<8; ++nf){
              int n = nb*64 + nf*8 + lc2;
              float2 gv = *(float2*)(sm + S_G + p*512 + n*4);
              int r0 = mb*32 + mf*16 + lr;
              sts2(sm, (u32)(r0*STR + n*2),     Dt[mf][nf][0]*gv.x, Dt[mf][nf][1]*gv.y);
              sts2(sm, (u32)((r0+8)*STR + n*2), Dt[mf][nf][2]*gv.x, Dt[mf][nf][3]*gv.y);
            }
          }
        } else {
          // L4 (compact tile: 16 rows, lo at +4352): warps 0-6 tangent, warp 7 primal
          const u32 wbl4 = wbh + 4352u;
          float D4[2][4];
          #pragma unroll
          for (int nf=0; nf<2; ++nf)
            #pragma unroll
            for (int r=0; r<4; ++r) D4[nf][r]=0.f;
          const u32 arow = (w<7) ? (u32)(w*16) : 112u;
          #pragma unroll 2
          for (int kc=0; kc<8; ++kc){
            const u32 kb = (u32)kc*32;
            u32 Ah[4], Al[4], Bh[4], Bl[4];
            ldm4(sb + S_A0 + arow*STR + kb + offA, Ah);
            ldm4(sb + S_A1 + arow*STR + kb + offA, Al);
            ldm4(wbh  + kb + offB, Bh);
            ldm4(wbl4 + kb + offB, Bl);
            mmaop(D4[0],Ah,Bh[0],Bh[1]); mmaop(D4[0],Al,Bh[0],Bh[1]); mmaop(D4[0],Ah,Bl[0],Bl[1]);
            mmaop(D4[1],Ah,Bh[2],Bh[3]); mmaop(D4[1],Al,Bh[2],Bh[3]); mmaop(D4[1],Ah,Bl[2],Bl[3]);
          }
          __syncthreads();   // A reads done before next stage-input writes
          if (w<7){
            #pragma unroll
            for (int nf=0; nf<2; ++nf)
              #pragma unroll
              for (int r=0; r<4; ++r){ uu[nf][r]=D4[nf][r]; usum[nf][r]+=wgt*D4[nf][r]; }
          } else {
            #pragma unroll
            for (int nf=0; nf<2; ++nf){
              int n = nf*8 + lc2;
              kst[nf][0]=D4[nf][0]+b4[n]; kst[nf][1]=D4[nf][1]+b4[n+1];
              kst[nf][2]=D4[nf][2]+b4[n]; kst[nf][3]=D4[nf][3]+b4[n+1];
              #pragma unroll
              for (int r=0; r<4; ++r) ksum[nf][r]+=wgt*kst[nf][r];
            }
          }
        }
        wp ^= 1;
      } // layers
    } // stages

    #pragma unroll
    for (int nf=0; nf<2; ++nf)
      #pragma unroll
      for (int r=0; r<4; ++r){ v[nf][r] += f6*usum[nf][r]; zz[nf][r] += f6*ksum[nf][r]; }
  } // steps

  // outputs
  if (w<7 && (P0+w) < NB){
    #pragma unroll
    for (int nf=0; nf<2; ++nf)
      #pragma unroll
      for (int r=0; r<4; ++r){
        int dir = lr + ((r>=2)?8:0), comp = nf*8 + lc2 + (r&1);
        g_V[(P0+w)*256 + dir*16 + comp] = v[nf][r];
      }
  }
  if (w==7 && pval){
    #pragma unroll
    for (int nf=0; nf<2; ++nf){
      int n = nf*8 + lc2;
      g_y [(P0+lr)*16 + n  ] = zz[nf][0];
      g_y [(P0+lr)*16 + n+1] = zz[nf][1];
      g_ys[(P0+lr)*16 + n  ] = zz[nf][2];
      g_ys[(P0+lr)*16 + n+1] = zz[nf][3];
    }
  }
}

// ============== finalize: one warp per point, lane j owns row j ==============
__global__ __launch_bounds__(256)
void finalize2(float* __restrict__ out)
{
  __shared__ float tp[8][17*16];
  const int wid = threadIdx.x >> 5, l = threadIdx.x & 31, j = l & 15;
  const int p = blockIdx.x*8 + wid;
  const unsigned FULL = 0xffffffffu;

  float R[16];
  {
    const float4* Vp = (const float4*)(g_V + p*256 + j*16);
    #pragma unroll
    for (int q=0; q<4; ++q){ float4 t = Vp[q];
      R[q*4]=t.x; R[q*4+1]=t.y; R[q*4+2]=t.z; R[q*4+3]=t.w; }
  }
  float gph[16], n2 = 0.f;
  #pragma unroll
  for (int i=0;i<16;++i){ float d = g_y[p*16+i]-g_ys[p*16+i]; gph[i]=d; n2+=d*d; }
  float inv = 1.f/(sqrtf(n2)+1e-8f);
  #pragma unroll
  for (int i=0;i<16;++i) gph[i]*=inv;
  float gx = 0.f;
  #pragma unroll
  for (int i=0;i<16;++i) gx += R[i]*gph[i];

  float A[16];
  #pragma unroll
  for (int k=0;k<16;++k){
    float s = 0.f;
    #pragma unroll
    for (int i=0;i<16;++i) s += R[i]*__shfl_sync(FULL, R[i], k);
    A[k] = s + ((k==j)?1e-6f:0.f);
  }

  #pragma unroll
  for (int k=0;k<16;++k){
    float akk = __shfl_sync(FULL, A[k], k);
    float dk  = sqrtf(fmaxf(akk, 1e-30f));
    float idk = 1.f/dk;
    float cand = A[k]*idk;
    A[k] = (j>=k)? cand : A[k];
    float mylk = (j>k)? A[k] : 0.f;
    #pragma unroll
    for (int i=k+1;i<16;++i){
      float lik = __shfl_sync(FULL, A[k], i);
      A[i] -= mylk*lik;
    }
  }

  float acc = 0.f, yvj = 0.f;
  #pragma unroll
  for (int i=0;i<16;++i){
    float num = __shfl_sync(FULL, gx - acc, i);
    float di  = __shfl_sync(FULL, A[i], i);
    float yvi = num/di;
    if (j==i) yvj = yvi;
    acc += ((j>i)? A[i] : 0.f)*yvi;
  }

  if (l < 16){
    #pragma unroll
    for (int i=0;i<16;++i) tp[wid][j*17 + i] = A[i];
  }
  __syncwarp();
  float U[16];
  #pragma unroll
  for (int i=0;i<16;++i) U[i] = tp[wid][i*17 + j];

  float acc2 = 0.f, sj = 0.f;
  #pragma unroll
  for (int i=15;i>=0;--i){
    float num = __shfl_sync(FULL, yvj - acc2, i);
    float di  = __shfl_sync(FULL, U[i], i);
    float si  = num/di;
    if (j==i) sj = si;
    acc2 += ((j<i)? U[i] : 0.f)*si;
  }
  if (l < 16) out[p*16 + j] = -sj;
}

extern "C" void kernel_launch(void* const* d_in, const int* in_sizes, int n_in,
                              void* d_out, int out_size)
{
  const float* x  = (const float*)d_in[0];
  const float* xs = (const float*)d_in[1];
  const float* W0 = (const float*)d_in[2];
  const float* b0 = (const float*)d_in[3];
  const float* W1 = (const float*)d_in[4];
  const float* b1 = (const float*)d_in[5];
  const float* W2 = (const float*)d_in[6];
  const float* b2 = (const float*)d_in[7];
  const float* W3 = (const float*)d_in[8];
  const float* b3 = (const float*)d_in[9];
  const float* W4 = (const float*)d_in[10];
  const float* b4 = (const float*)d_in[11];
  float* out = (float*)d_out;

  prep<<<204,256>>>(W0,W1,W2,W3,W4);
  cudaFuncSetAttribute(flow, cudaFuncAttributeMaxDynamicSharedMemorySize, S_TOT);
  flow<<<147,256,S_TOT>>>(x,xs,b0,b1,b2,b3,b4);
  finalize2<<<128,256>>>(out);
}

// round 16
// speedup vs baseline: 1.2828x; 1.2435x over previous
#include <cuda_runtime.h>
#include <cuda_fp16.h>
#include <math.h>

#define NB 1024
#define NSTEPS 10
typedef unsigned int u32;

#define STR   272
#define WBYTES 34816
#define S_A0  0
#define S_A1  34816
#define S_W   69632
#define S_G   139264
#define S_TOT 143360

__device__ float g_y[NB*16], g_ys[NB*16], g_V[NB*256];
__device__ __align__(16) __half g_Wt[3][17408];  // hidden layers 1-3, hi only: [128][136]
__device__ __align__(16) __half g_W0c[5120];     // L0 compact hi: 128 rows x 40 halves (80B stride)
__device__ __align__(16) __half g_W4c[2176];     // L4 compact hi: 16 rows x 136 halves

__global__ void prep(const float* __restrict__ W0, const float* __restrict__ W1,
                     const float* __restrict__ W2, const float* __restrict__ W3,
                     const float* __restrict__ W4)
{
  int i = blockIdx.x*256 + threadIdx.x;
  if (i < 3*128*136){
    int l = i/(128*136), r = i%(128*136), n = r/136, k = r%136;
    const float* W = (l==0)?W1:(l==1)?W2:W3;
    float w = (k<128)? W[k*128+n] : 0.f;
    g_Wt[l][n*136+k] = __float2half_rn(w);
  }
  if (i < 128*32){           // L0 compact
    int n = i>>5, k = i&31;
    float w = (k<17)? W0[k*128+n] : 0.f;
    g_W0c[n*40+k] = __float2half_rn(w);
  }
  if (i < 16*136){           // L4 compact
    int n = i/136, k = i%136;
    float w = (k<128)? W4[k*16+n] : 0.f;
    g_W4c[n*136+k] = __float2half_rn(w);
  }
}

__device__ __forceinline__ u32 s2u(const void* p){ u32 a;
  asm("{.reg .u64 t; cvta.to.shared.u64 t,%1; cvt.u32.u64 %0,t;}":"=r"(a):"l"(p)); return a; }
__device__ __forceinline__ void ldm4(u32 a, u32 r[4]){
  asm volatile("ldmatrix.sync.aligned.m8n8.x4.shared.b16 {%0,%1,%2,%3},[%4];"
    :"=r"(r[0]),"=r"(r[1]),"=r"(r[2]),"=r"(r[3]):"r"(a)); }
__device__ __forceinline__ void mmaop(float d[4], const u32 a[4], u32 b0, u32 b1){
  asm volatile("mma.sync.aligned.m16n8k16.row.col.f32.f16.f16.f32 "
    "{%0,%1,%2,%3},{%4,%5,%6,%7},{%8,%9},{%0,%1,%2,%3};"
    :"+f"(d[0]),"+f"(d[1]),"+f"(d[2]),"+f"(d[3])
    :"r"(a[0]),"r"(a[1]),"r"(a[2]),"r"(a[3]),"r"(b0),"r"(b1)); }
#define CPASYNC(dst,src) asm volatile("cp.async.cg.shared.global [%0],[%1],16;"::"r"(dst),"l"(src):"memory")
#define CPCOMMIT() asm volatile("cp.async.commit_group;":::"memory")
#define CPWAIT()   asm volatile("cp.async.wait_group 0;":::"memory")

__device__ __forceinline__ void sts2(char* sm, u32 o, float a, float b){
  __half ha=__float2half_rn(a), hb=__float2half_rn(b);
  __half la=__float2half_rn(a-__half2float(ha)), lb=__float2half_rn(b-__half2float(hb));
  *(__half2*)(sm + S_A0 + o) = __halves2half2(ha,hb);
  *(__half2*)(sm + S_A1 + o) = __halves2half2(la,lb);
}

// tanh via ex2/rcp approx: abs err ~1e-7, saturates correctly
__device__ __forceinline__ float ftanh(float x){
  float t; asm("ex2.approx.f32 %0, %1;" : "=f"(t) : "f"(x*2.8853900817779268f));
  float r; asm("rcp.approx.f32 %0, %1;" : "=f"(r) : "f"(t+1.f));
  return fmaf(-2.f, r, 1.f);
}

// inner g-block: 4 ldm4 (B hi) + up to 8 mma (2-pass: AhBh + AlBh)
#define GBLOCK(WBH, RSTR, OB, DOM0) \
  _Pragma("unroll") \
  for (int g=0; g<4; ++g){ \
    u32 Bh[4]; \
    ldm4((WBH) + (u32)((nb*64+g*16)*(RSTR)) + kb + (OB), Bh); \
    if (DOM0){ \
      mmaop(Dt[0][g*2  ], Ah[0], Bh[0],Bh[1]); \
      mmaop(Dt[0][g*2  ], Al[0], Bh[0],Bh[1]); \
      mmaop(Dt[0][g*2+1], Ah[0], Bh[2],Bh[3]); \
      mmaop(Dt[0][g*2+1], Al[0], Bh[2],Bh[3]); \
    } \
    mmaop(Dt[1][g*2  ], Ah[1], Bh[0],Bh[1]); \
    mmaop(Dt[1][g*2  ], Al[1], Bh[0],Bh[1]); \
    mmaop(Dt[1][g*2+1], Ah[1], Bh[2],Bh[3]); \
    mmaop(Dt[1][g*2+1], Al[1], Bh[2],Bh[3]); \
  }

__global__ __launch_bounds__(256,1)
void flow(const float* __restrict__ x,  const float* __restrict__ xs,
          const float* __restrict__ b0, const float* __restrict__ b1,
          const float* __restrict__ b2, const float* __restrict__ b3,
          const float* __restrict__ b4)
{
  extern __shared__ char sm[];
  const u32 sb = s2u(sm);
  const int tid = threadIdx.x, w = tid>>5, l = tid&31;
  const int P0 = blockIdx.x*7;                    // 147 CTAs x 7 points
  const int mb = w>>1, nb = w&1;                  // mb3 warps = w6,w7
  const int lr = l>>2, lc2 = (l&3)*2;

  const u32 offA  = (u32)(l&15)*STR + (u32)(l>>4)*16;
  const u32 offB  = ((u32)(l&7) + ((u32)(l>>4)&1)*8)*STR + (((u32)l>>3)&1)*16;
  const u32 offB0 = ((u32)(l&7) + ((u32)(l>>4)&1)*8)*80u + (((u32)l>>3)&1)*16;

  // state: w<7 -> tangent of point P0+w ; w==7 -> 16 trajectories (J rows 112-119, star 120-127)
  float v[2][4], uu[2][4], usum[2][4], zz[2][4], kst[2][4], ksum[2][4];
  #pragma unroll
  for (int nf=0; nf<2; ++nf)
    #pragma unroll
    for (int r=0; r<4; ++r){
      int dir = lr + ((r>=2)?8:0), comp = nf*8 + lc2 + (r&1);
      v[nf][r] = (dir==comp)?1.f:0.f; uu[nf][r]=0.f;
      zz[nf][r]=0.f; kst[nf][r]=0.f;
    }
  const bool pval = (lr<7) && (P0+lr < NB);
  if (w==7 && pval){
    #pragma unroll
    for (int nf=0; nf<2; ++nf){
      int n = nf*8 + lc2;
      zz[nf][0] = x [(P0+lr)*16 + n];   zz[nf][1] = x [(P0+lr)*16 + n+1];
      zz[nf][2] = xs[(P0+lr)*16 + n];   zz[nf][3] = xs[(P0+lr)*16 + n+1];
    }
  }

  { // initial W prefetch (layer 0 compact hi -> buf 0)
    const char* src = (const char*)g_W0c;
    u32 dst = sb + S_W;
    for (int i=tid; i<640; i+=256) CPASYNC(dst + i*16, src + i*16);
    CPCOMMIT();
  }
  int wp = 0;
  const float dt = 1.f/NSTEPS, f6 = dt/6.f;

  for (int step=0; step<NSTEPS; ++step){
    const float t0 = step*dt;
    #pragma unroll
    for (int nf=0; nf<2; ++nf)
      #pragma unroll
      for (int r=0; r<4; ++r){ usum[nf][r]=0.f; ksum[nf][r]=0.f; }

    for (int s=0; s<4; ++s){
      const float cs = (s==0)?0.f:((s==3)?dt:0.5f*dt);
      const float ts = t0+cs, wgt = (s==0||s==3)?1.f:2.f;

      // ---- stage inputs ----
      if (w<7){
        #pragma unroll
        for (int nf=0; nf<2; ++nf){
          int n = nf*8 + lc2;
          sts2(sm, (u32)((w*16+lr  )*STR + n*2), v[nf][0]+cs*uu[nf][0], v[nf][1]+cs*uu[nf][1]);
          sts2(sm, (u32)((w*16+lr+8)*STR + n*2), v[nf][2]+cs*uu[nf][2], v[nf][3]+cs*uu[nf][3]);
        }
      } else {
        #pragma unroll
        for (int nf=0; nf<2; ++nf){
          int n = nf*8 + lc2;
          sts2(sm, (u32)((112+lr)*STR + n*2), zz[nf][0]+cs*kst[nf][0], zz[nf][1]+cs*kst[nf][1]);
          sts2(sm, (u32)((120+lr)*STR + n*2), zz[nf][2]+cs*kst[nf][2], zz[nf][3]+cs*kst[nf][3]);
        }
        if (l<16){
          int row = 112+l; uint4 z4 = make_uint4(0,0,0,0);
          *(uint4*)(sm + S_A0 + row*STR + 32) = z4; *(uint4*)(sm + S_A0 + row*STR + 48) = z4;
          *(uint4*)(sm + S_A1 + row*STR + 32) = z4; *(uint4*)(sm + S_A1 + row*STR + 48) = z4;
        }
        __syncwarp();
        if (l<16){
          int row = 112+l;
          __half th = __float2half_rn(ts);
          *(__half*)(sm + S_A0 + row*STR + 32) = th;
          *(__half*)(sm + S_A1 + row*STR + 32) = __float2half_rn(ts - __half2float(th));
        }
      }

      for (int ly=0; ly<5; ++ly){
        CPWAIT();
        __syncthreads();   // W[ly] ready; A writes visible
        if (!(step==NSTEPS-1 && s==3 && ly==4)){
          const int nxt = (ly+1)%5;
          const char* src; int n4;
          if (nxt==0){ src = (const char*)g_W0c; n4 = 640; }
          else if (nxt==4){ src = (const char*)g_W4c; n4 = 272; }
          else { src = (const char*)g_Wt[nxt-1]; n4 = 2176; }
          u32 dst = sb + S_W + (u32)(wp^1)*WBYTES;
          for (int i=tid; i<n4; i+=256) CPASYNC(dst + i*16, src + i*16);
          CPCOMMIT();
        }
        const u32 wbh = sb + S_W + (u32)wp*WBYTES;

        if (ly<4){
          float Dt[2][8][4];
          #pragma unroll
          for (int mf=0; mf<2; ++mf)
            #pragma unroll
            for (int nf=0; nf<8; ++nf)
              #pragma unroll
              for (int r=0; r<4; ++r) Dt[mf][nf][r]=0.f;

          if (ly==0){
            // L0: compact B tile, constant stride 80
            const int KCfull = (mb==3)?2:1;
            #pragma unroll 2
            for (int kc=0; kc<KCfull; ++kc){
              const u32 kb = (u32)kc*32;
              const bool doM0 = (kc==0);
              u32 Ah[2][4], Al[2][4];
              if (doM0){
                ldm4(sb + S_A0 + (u32)(mb*32)*STR + kb + offA, Ah[0]);
                ldm4(sb + S_A1 + (u32)(mb*32)*STR + kb + offA, Al[0]);
              }
              ldm4(sb + S_A0 + (u32)(mb*32+16)*STR + kb + offA, Ah[1]);
              ldm4(sb + S_A1 + (u32)(mb*32+16)*STR + kb + offA, Al[1]);
              GBLOCK(wbh, 80, offB0, doM0)
            }
          } else {
            // layers 1-3: full B tile, constant stride STR
            #pragma unroll 2
            for (int kc=0; kc<8; ++kc){
              const u32 kb = (u32)kc*32;
              u32 Ah[2][4], Al[2][4];
              ldm4(sb + S_A0 + (u32)(mb*32)*STR + kb + offA, Ah[0]);
              ldm4(sb + S_A1 + (u32)(mb*32)*STR + kb + offA, Al[0]);
              ldm4(sb + S_A0 + (u32)(mb*32+16)*STR + kb + offA, Ah[1]);
              ldm4(sb + S_A1 + (u32)(mb*32+16)*STR + kb + offA, Al[1]);
              GBLOCK(wbh, STR, offB, true)
            }
          }
          __syncthreads();   // all mma reads of A done
          // phase 1: primal bias+tanh (mb==3 warps: mf=1 rows are trajectories)
          const float* bias = (ly==0)?b0:(ly==1)?b1:(ly==2)?b2:b3;
          if (mb==3){
            #pragma unroll
            for (int nf=0; nf<8; ++nf){
              int n = nb*64 + nf*8 + lc2;
              float bx = bias[n], by = bias[n+1];
              float hJ0=ftanh(Dt[1][nf][0]+bx), hJ1=ftanh(Dt[1][nf][1]+by);
              float hS0=ftanh(Dt[1][nf][2]+bx), hS1=ftanh(Dt[1][nf][3]+by);
              sts2(sm, (u32)((112+lr)*STR + n*2), hJ0, hJ1);
              sts2(sm, (u32)((120+lr)*STR + n*2), hS0, hS1);
              *(float2*)(sm + S_G + lr*512 + n*4) = make_float2(1.f-hJ0*hJ0, 1.f-hJ1*hJ1);
            }
          }
          __syncthreads();
          // phase 2: tangent scale-by-g -> next A (mb3 warps: mf=0 only)
          #pragma unroll
          for (int mf=0; mf<2; ++mf){
            if (mb==3 && mf==1) break;
            int p = mb*2 + mf;
            #pragma unroll
            for (int nf=0; nf<8; ++nf){
              int n = nb*64 + nf*8 + lc2;
              float2 gv = *(float2*)(sm + S_G + p*512 + n*4);
              int r0 = mb*32 + mf*16 + lr;
              sts2(sm, (u32)(r0*STR + n*2),     Dt[mf][nf][0]*gv.x, Dt[mf][nf][1]*gv.y);
              sts2(sm, (u32)((r0+8)*STR + n*2), Dt[mf][nf][2]*gv.x, Dt[mf][nf][3]*gv.y);
            }
          }
        } else {
          // L4 (compact hi tile: 16 rows): warps 0-6 tangent, warp 7 primal
          float D4[2][4];
          #pragma unroll
          for (int nf=0; nf<2; ++nf)
            #pragma unroll
            for (int r=0; r<4; ++r) D4[nf][r]=0.f;
          const u32 arow = (w<7) ? (u32)(w*16) : 112u;
          #pragma unroll 2
          for (int kc=0; kc<8; ++kc){
            const u32 kb = (u32)kc*32;
            u32 Ah[4], Al[4], Bh[4];
            ldm4(sb + S_A0 + arow*STR + kb + offA, Ah);
            ldm4(sb + S_A1 + arow*STR + kb + offA, Al);
            ldm4(wbh + kb + offB, Bh);
            mmaop(D4[0],Ah,Bh[0],Bh[1]); mmaop(D4[0],Al,Bh[0],Bh[1]);
            mmaop(D4[1],Ah,Bh[2],Bh[3]); mmaop(D4[1],Al,Bh[2],Bh[3]);
          }
          __syncthreads();   // A reads done before next stage-input writes
          if (w<7){
            #pragma unroll
            for (int nf=0; nf<2; ++nf)
              #pragma unroll
              for (int r=0; r<4; ++r){ uu[nf][r]=D4[nf][r]; usum[nf][r]+=wgt*D4[nf][r]; }
          } else {
            #pragma unroll
            for (int nf=0; nf<2; ++nf){
              int n = nf*8 + lc2;
              kst[nf][0]=D4[nf][0]+b4[n]; kst[nf][1]=D4[nf][1]+b4[n+1];
              kst[nf][2]=D4[nf][2]+b4[n]; kst[nf][3]=D4[nf][3]+b4[n+1];
              #pragma unroll
              for (int r=0; r<4; ++r) ksum[nf][r]+=wgt*kst[nf][r];
            }
          }
        }
        wp ^= 1;
      } // layers
    } // stages

    #pragma unroll
    for (int nf=0; nf<2; ++nf)
      #pragma unroll
      for (int r=0; r<4; ++r){ v[nf][r] += f6*usum[nf][r]; zz[nf][r] += f6*ksum[nf][r]; }
  } // steps

  // outputs
  if (w<7 && (P0+w) < NB){
    #pragma unroll
    for (int nf=0; nf<2; ++nf)
      #pragma unroll
      for (int r=0; r<4; ++r){
        int dir = lr + ((r>=2)?8:0), comp = nf*8 + lc2 + (r&1);
        g_V[(P0+w)*256 + dir*16 + comp] = v[nf][r];
      }
  }
  if (w==7 && pval){
    #pragma unroll
    for (int nf=0; nf<2; ++nf){
      int n = nf*8 + lc2;
      g_y [(P0+lr)*16 + n  ] = zz[nf][0];
      g_y [(P0+lr)*16 + n+1] = zz[nf][1];
      g_ys[(P0+lr)*16 + n  ] = zz[nf][2];
      g_ys[(P0+lr)*16 + n+1] = zz[nf][3];
    }
  }
}

// ============== finalize: one warp per point, lane j owns row j ==============
__global__ __launch_bounds__(256)
void finalize2(float* __restrict__ out)
{
  __shared__ float tp[8][17*16];
  const int wid = threadIdx.x >> 5, l = threadIdx.x & 31, j = l & 15;
  const int p = blockIdx.x*8 + wid;
  const unsigned FULL = 0xffffffffu;

  float R[16];
  {
    const float4* Vp = (const float4*)(g_V + p*256 + j*16);
    #pragma unroll
    for (int q=0; q<4; ++q){ float4 t = Vp[q];
      R[q*4]=t.x; R[q*4+1]=t.y; R[q*4+2]=t.z; R[q*4+3]=t.w; }
  }
  float gph[16], n2 = 0.f;
  #pragma unroll
  for (int i=0;i<16;++i){ float d = g_y[p*16+i]-g_ys[p*16+i]; gph[i]=d; n2+=d*d; }
  float inv = 1.f/(sqrtf(n2)+1e-8f);
  #pragma unroll
  for (int i=0;i<16;++i) gph[i]*=inv;
  float gx = 0.f;
  #pragma unroll
  for (int i=0;i<16;++i) gx += R[i]*gph[i];

  float A[16];
  #pragma unroll
  for (int k=0;k<16;++k){
    float s = 0.f;
    #pragma unroll
    for (int i=0;i<16;++i) s += R[i]*__shfl_sync(FULL, R[i], k);
    A[k] = s + ((k==j)?1e-6f:0.f);
  }

  #pragma unroll
  for (int k=0;k<16;++k){
    float akk = __shfl_sync(FULL, A[k], k);
    float dk  = sqrtf(fmaxf(akk, 1e-30f));
    float idk = 1.f/dk;
    float cand = A[k]*idk;
    A[k] = (j>=k)? cand : A[k];
    float mylk = (j>k)? A[k] : 0.f;
    #pragma unroll
    for (int i=k+1;i<16;++i){
      float lik = __shfl_sync(FULL, A[k], i);
      A[i] -= mylk*lik;
    }
  }

  float acc = 0.f, yvj = 0.f;
  #pragma unroll
  for (int i=0;i<16;++i){
    float num = __shfl_sync(FULL, gx - acc, i);
    float di  = __shfl_sync(FULL, A[i], i);
    float yvi = num/di;
    if (j==i) yvj = yvi;
    acc += ((j>i)? A[i] : 0.f)*yvi;
  }

  if (l < 16){
    #pragma unroll
    for (int i=0;i<16;++i) tp[wid][j*17 + i] = A[i];
  }
  __syncwarp();
  float U[16];
  #pragma unroll
  for (int i=0;i<16;++i) U[i] = tp[wid][i*17 + j];

  float acc2 = 0.f, sj = 0.f;
  #pragma unroll
  for (int i=15;i>=0;--i){
    float num = __shfl_sync(FULL, yvj - acc2, i);
    float di  = __shfl_sync(FULL, U[i], i);
    float si  = num/di;
    if (j==i) sj = si;
    acc2 += ((j<i)? U[i] : 0.f)*si;
  }
  if (l < 16) out[p*16 + j] = -sj;
}

extern "C" void kernel_launch(void* const* d_in, const int* in_sizes, int n_in,
                              void* d_out, int out_size)
{
  const float* x  = (const float*)d_in[0];
  const float* xs = (const float*)d_in[1];
  const float* W0 = (const float*)d_in[2];
  const float* b0 = (const float*)d_in[3];
  const float* W1 = (const float*)d_in[4];
  const float* b1 = (const float*)d_in[5];
  const float* W2 = (const float*)d_in[6];
  const float* b2 = (const float*)d_in[7];
  const float* W3 = (const float*)d_in[8];
  const float* b3 = (const float*)d_in[9];
  const float* W4 = (const float*)d_in[10];
  const float* b4 = (const float*)d_in[11];
  float* out = (float*)d_out;

  prep<<<204,256>>>(W0,W1,W2,W3,W4);
  cudaFuncSetAttribute(flow, cudaFuncAttributeMaxDynamicSharedMemorySize, S_TOT);
  flow<<<147,256,S_TOT>>>(x,xs,b0,b1,b2,b3,b4);
  finalize2<<<128,256>>>(out);
}

// round 17
// speedup vs baseline: 1.9345x; 1.5080x over previous
#include <cuda_runtime.h>
#include <cuda_fp16.h>
#include <math.h>

#define NB 1024
#define NSTEPS 10
typedef unsigned int u32;

#define STR   272
#define WBYTES 34816
#define S_A0  0
#define S_W   34816
#define S_G   104448
#define S_TOT 108544

__device__ float g_y[NB*16], g_ys[NB*16], g_V[NB*256];
__device__ __align__(16) __half g_Wt[3][17408];  // hidden layers 1-3: [128][136]
__device__ __align__(16) __half g_W0c[5120];     // L0 compact: 128 rows x 40 halves (80B stride)
__device__ __align__(16) __half g_W4c[2176];     // L4 compact: 16 rows x 136 halves

__global__ void prep(const float* __restrict__ W0, const float* __restrict__ W1,
                     const float* __restrict__ W2, const float* __restrict__ W3,
                     const float* __restrict__ W4)
{
  int i = blockIdx.x*256 + threadIdx.x;
  if (i < 3*128*136){
    int l = i/(128*136), r = i%(128*136), n = r/136, k = r%136;
    const float* W = (l==0)?W1:(l==1)?W2:W3;
    float w = (k<128)? W[k*128+n] : 0.f;
    g_Wt[l][n*136+k] = __float2half_rn(w);
  }
  if (i < 128*32){           // L0 compact
    int n = i>>5, k = i&31;
    float w = (k<17)? W0[k*128+n] : 0.f;
    g_W0c[n*40+k] = __float2half_rn(w);
  }
  if (i < 16*136){           // L4 compact
    int n = i/136, k = i%136;
    float w = (k<128)? W4[k*16+n] : 0.f;
    g_W4c[n*136+k] = __float2half_rn(w);
  }
}

__device__ __forceinline__ u32 s2u(const void* p){ u32 a;
  asm("{.reg .u64 t; cvta.to.shared.u64 t,%1; cvt.u32.u64 %0,t;}":"=r"(a):"l"(p)); return a; }
__device__ __forceinline__ void ldm4(u32 a, u32 r[4]){
  asm volatile("ldmatrix.sync.aligned.m8n8.x4.shared.b16 {%0,%1,%2,%3},[%4];"
    :"=r"(r[0]),"=r"(r[1]),"=r"(r[2]),"=r"(r[3]):"r"(a)); }
__device__ __forceinline__ void mmaop(float d[4], const u32 a[4], u32 b0, u32 b1){
  asm volatile("mma.sync.aligned.m16n8k16.row.col.f32.f16.f16.f32 "
    "{%0,%1,%2,%3},{%4,%5,%6,%7},{%8,%9},{%0,%1,%2,%3};"
    :"+f"(d[0]),"+f"(d[1]),"+f"(d[2]),"+f"(d[3])
    :"r"(a[0]),"r"(a[1]),"r"(a[2]),"r"(a[3]),"r"(b0),"r"(b1)); }
#define CPASYNC(dst,src) asm volatile("cp.async.cg.shared.global [%0],[%1],16;"::"r"(dst),"l"(src):"memory")
#define CPCOMMIT() asm volatile("cp.async.commit_group;":::"memory")
#define CPWAIT()   asm volatile("cp.async.wait_group 0;":::"memory")

// single fp16 pair store (A tile is pure fp16 now)
__device__ __forceinline__ void stA(char* sm, u32 o, float a, float b){
  *(__half2*)(sm + S_A0 + o) = __halves2half2(__float2half_rn(a), __float2half_rn(b));
}

// tanh via ex2/rcp approx: abs err ~1e-7, saturates correctly
__device__ __forceinline__ float ftanh(float x){
  float t; asm("ex2.approx.f32 %0, %1;" : "=f"(t) : "f"(x*2.8853900817779268f));
  float r; asm("rcp.approx.f32 %0, %1;" : "=f"(r) : "f"(t+1.f));
  return fmaf(-2.f, r, 1.f);
}

// inner g-block: 1 ldm4 (B) + up to 4 mma (single pass, fp16 operands)
#define GBLOCK(WBH, RSTR, OB, DOM0) \
  _Pragma("unroll") \
  for (int g=0; g<4; ++g){ \
    u32 Bh[4]; \
    ldm4((WBH) + (u32)((nb*64+g*16)*(RSTR)) + kb + (OB), Bh); \
    if (DOM0){ \
      mmaop(Dt[0][g*2  ], Ah[0], Bh[0],Bh[1]); \
      mmaop(Dt[0][g*2+1], Ah[0], Bh[2],Bh[3]); \
    } \
    mmaop(Dt[1][g*2  ], Ah[1], Bh[0],Bh[1]); \
    mmaop(Dt[1][g*2+1], Ah[1], Bh[2],Bh[3]); \
  }

__global__ __launch_bounds__(256,1)
void flow(const float* __restrict__ x,  const float* __restrict__ xs,
          const float* __restrict__ b0, const float* __restrict__ b1,
          const float* __restrict__ b2, const float* __restrict__ b3,
          const float* __restrict__ b4)
{
  extern __shared__ char sm[];
  const u32 sb = s2u(sm);
  const int tid = threadIdx.x, w = tid>>5, l = tid&31;
  const int P0 = blockIdx.x*7;                    // 147 CTAs x 7 points
  const int mb = w>>1, nb = w&1;                  // mb3 warps = w6,w7
  const int lr = l>>2, lc2 = (l&3)*2;

  const u32 offA  = (u32)(l&15)*STR + (u32)(l>>4)*16;
  const u32 offB  = ((u32)(l&7) + ((u32)(l>>4)&1)*8)*STR + (((u32)l>>3)&1)*16;
  const u32 offB0 = ((u32)(l&7) + ((u32)(l>>4)&1)*8)*80u + (((u32)l>>3)&1)*16;

  // state: w<7 -> tangent of point P0+w ; w==7 -> 16 trajectories (J rows 112-119, star 120-127)
  float v[2][4], uu[2][4], usum[2][4], zz[2][4], kst[2][4], ksum[2][4];
  #pragma unroll
  for (int nf=0; nf<2; ++nf)
    #pragma unroll
    for (int r=0; r<4; ++r){
      int dir = lr + ((r>=2)?8:0), comp = nf*8 + lc2 + (r&1);
      v[nf][r] = (dir==comp)?1.f:0.f; uu[nf][r]=0.f;
      zz[nf][r]=0.f; kst[nf][r]=0.f;
    }
  const bool pval = (lr<7) && (P0+lr < NB);
  if (w==7 && pval){
    #pragma unroll
    for (int nf=0; nf<2; ++nf){
      int n = nf*8 + lc2;
      zz[nf][0] = x [(P0+lr)*16 + n];   zz[nf][1] = x [(P0+lr)*16 + n+1];
      zz[nf][2] = xs[(P0+lr)*16 + n];   zz[nf][3] = xs[(P0+lr)*16 + n+1];
    }
  }

  { // initial W prefetch (layer 0 compact -> buf 0)
    const char* src = (const char*)g_W0c;
    u32 dst = sb + S_W;
    for (int i=tid; i<640; i+=256) CPASYNC(dst + i*16, src + i*16);
    CPCOMMIT();
  }
  int wp = 0;
  const float dt = 1.f/NSTEPS, f6 = dt/6.f;

  for (int step=0; step<NSTEPS; ++step){
    const float t0 = step*dt;
    #pragma unroll
    for (int nf=0; nf<2; ++nf)
      #pragma unroll
      for (int r=0; r<4; ++r){ usum[nf][r]=0.f; ksum[nf][r]=0.f; }

    for (int s=0; s<4; ++s){
      const float cs = (s==0)?0.f:((s==3)?dt:0.5f*dt);
      const float ts = t0+cs, wgt = (s==0||s==3)?1.f:2.f;

      // ---- stage inputs ----
      if (w<7){
        #pragma unroll
        for (int nf=0; nf<2; ++nf){
          int n = nf*8 + lc2;
          stA(sm, (u32)((w*16+lr  )*STR + n*2), v[nf][0]+cs*uu[nf][0], v[nf][1]+cs*uu[nf][1]);
          stA(sm, (u32)((w*16+lr+8)*STR + n*2), v[nf][2]+cs*uu[nf][2], v[nf][3]+cs*uu[nf][3]);
        }
      } else {
        #pragma unroll
        for (int nf=0; nf<2; ++nf){
          int n = nf*8 + lc2;
          stA(sm, (u32)((112+lr)*STR + n*2), zz[nf][0]+cs*kst[nf][0], zz[nf][1]+cs*kst[nf][1]);
          stA(sm, (u32)((120+lr)*STR + n*2), zz[nf][2]+cs*kst[nf][2], zz[nf][3]+cs*kst[nf][3]);
        }
        if (l<16){
          int row = 112+l; uint4 z4 = make_uint4(0,0,0,0);
          *(uint4*)(sm + S_A0 + row*STR + 32) = z4; *(uint4*)(sm + S_A0 + row*STR + 48) = z4;
        }
        __syncwarp();
        if (l<16){
          int row = 112+l;
          *(__half*)(sm + S_A0 + row*STR + 32) = __float2half_rn(ts);
        }
      }

      for (int ly=0; ly<5; ++ly){
        CPWAIT();
        __syncthreads();   // W[ly] ready; A writes visible
        if (!(step==NSTEPS-1 && s==3 && ly==4)){
          const int nxt = (ly+1)%5;
          const char* src; int n4;
          if (nxt==0){ src = (const char*)g_W0c; n4 = 640; }
          else if (nxt==4){ src = (const char*)g_W4c; n4 = 272; }
          else { src = (const char*)g_Wt[nxt-1]; n4 = 2176; }
          u32 dst = sb + S_W + (u32)(wp^1)*WBYTES;
          for (int i=tid; i<n4; i+=256) CPASYNC(dst + i*16, src + i*16);
          CPCOMMIT();
        }
        const u32 wbh = sb + S_W + (u32)wp*WBYTES;

        if (ly<4){
          float Dt[2][8][4];
          #pragma unroll
          for (int mf=0; mf<2; ++mf)
            #pragma unroll
            for (int nf=0; nf<8; ++nf)
              #pragma unroll
              for (int r=0; r<4; ++r) Dt[mf][nf][r]=0.f;

          if (ly==0){
            // L0: compact B tile, constant stride 80
            const int KCfull = (mb==3)?2:1;
            #pragma unroll 2
            for (int kc=0; kc<KCfull; ++kc){
              const u32 kb = (u32)kc*32;
              const bool doM0 = (kc==0);
              u32 Ah[2][4];
              if (doM0) ldm4(sb + S_A0 + (u32)(mb*32)*STR + kb + offA, Ah[0]);
              ldm4(sb + S_A0 + (u32)(mb*32+16)*STR + kb + offA, Ah[1]);
              GBLOCK(wbh, 80, offB0, doM0)
            }
          } else {
            // layers 1-3: full B tile, constant stride STR
            #pragma unroll 2
            for (int kc=0; kc<8; ++kc){
              const u32 kb = (u32)kc*32;
              u32 Ah[2][4];
              ldm4(sb + S_A0 + (u32)(mb*32)*STR + kb + offA, Ah[0]);
              ldm4(sb + S_A0 + (u32)(mb*32+16)*STR + kb + offA, Ah[1]);
              GBLOCK(wbh, STR, offB, true)
            }
          }
          __syncthreads();   // all mma reads of A done
          // phase 1: primal bias+tanh (mb==3 warps: mf=1 rows are trajectories)
          const float* bias = (ly==0)?b0:(ly==1)?b1:(ly==2)?b2:b3;
          if (mb==3){
            #pragma unroll
            for (int nf=0; nf<8; ++nf){
              int n = nb*64 + nf*8 + lc2;
              float bx = bias[n], by = bias[n+1];
              float hJ0=ftanh(Dt[1][nf][0]+bx), hJ1=ftanh(Dt[1][nf][1]+by);
              float hS0=ftanh(Dt[1][nf][2]+bx), hS1=ftanh(Dt[1][nf][3]+by);
              stA(sm, (u32)((112+lr)*STR + n*2), hJ0, hJ1);
              stA(sm, (u32)((120+lr)*STR + n*2), hS0, hS1);
              *(float2*)(sm + S_G + lr*512 + n*4) = make_float2(1.f-hJ0*hJ0, 1.f-hJ1*hJ1);
            }
          }
          __syncthreads();
          // phase 2: tangent scale-by-g -> next A (mb3 warps: mf=0 only)
          #pragma unroll
          for (int mf=0; mf<2; ++mf){
            if (mb==3 && mf==1) break;
            int p = mb*2 + mf;
            #pragma unroll
            for (int nf=0; nf<8; ++nf){
              int n = nb*64 + nf*8 + lc2;
              float2 gv = *(float2*)(sm + S_G + p*512 + n*4);
              int r0 = mb*32 + mf*16 + lr;
              stA(sm, (u32)(r0*STR + n*2),     Dt[mf][nf][0]*gv.x, Dt[mf][nf][1]*gv.y);
              stA(sm, (u32)((r0+8)*STR + n*2), Dt[mf][nf][2]*gv.x, Dt[mf][nf][3]*gv.y);
            }
          }
        } else {
          // L4 (compact tile: 16 rows): warps 0-6 tangent, warp 7 primal
          float D4[2][4];
          #pragma unroll
          for (int nf=0; nf<2; ++nf)
            #pragma unroll
            for (int r=0; r<4; ++r) D4[nf][r]=0.f;
          const u32 arow = (w<7) ? (u32)(w*16) : 112u;
          #pragma unroll 2
          for (int kc=0; kc<8; ++kc){
            const u32 kb = (u32)kc*32;
            u32 Ah[4], Bh[4];
            ldm4(sb + S_A0 + arow*STR + kb + offA, Ah);
            ldm4(wbh + kb + offB, Bh);
            mmaop(D4[0],Ah,Bh[0],Bh[1]);
            mmaop(D4[1],Ah,Bh[2],Bh[3]);
          }
          __syncthreads();   // A reads done before next stage-input writes
          if (w<7){
            #pragma unroll
            for (int nf=0; nf<2; ++nf)
              #pragma unroll
              for (int r=0; r<4; ++r){ uu[nf][r]=D4[nf][r]; usum[nf][r]+=wgt*D4[nf][r]; }
          } else {
            #pragma unroll
            for (int nf=0; nf<2; ++nf){
              int n = nf*8 + lc2;
              kst[nf][0]=D4[nf][0]+b4[n]; kst[nf][1]=D4[nf][1]+b4[n+1];
              kst[nf][2]=D4[nf][2]+b4[n]; kst[nf][3]=D4[nf][3]+b4[n+1];
              #pragma unroll
              for (int r=0; r<4; ++r) ksum[nf][r]+=wgt*kst[nf][r];
            }
          }
        }
        wp ^= 1;
      } // layers
    } // stages

    #pragma unroll
    for (int nf=0; nf<2; ++nf)
      #pragma unroll
      for (int r=0; r<4; ++r){ v[nf][r] += f6*usum[nf][r]; zz[nf][r] += f6*ksum[nf][r]; }
  } // steps

  // outputs
  if (w<7 && (P0+w) < NB){
    #pragma unroll
    for (int nf=0; nf<2; ++nf)
      #pragma unroll
      for (int r=0; r<4; ++r){
        int dir = lr + ((r>=2)?8:0), comp = nf*8 + lc2 + (r&1);
        g_V[(P0+w)*256 + dir*16 + comp] = v[nf][r];
      }
  }
  if (w==7 && pval){
    #pragma unroll
    for (int nf=0; nf<2; ++nf){
      int n = nf*8 + lc2;
      g_y [(P0+lr)*16 + n  ] = zz[nf][0];
      g_y [(P0+lr)*16 + n+1] = zz[nf][1];
      g_ys[(P0+lr)*16 + n  ] = zz[nf][2];
      g_ys[(P0+lr)*16 + n+1] = zz[nf][3];
    }
  }
}

// ============== finalize: one warp per point, lane j owns row j ==============
__global__ __launch_bounds__(256)
void finalize2(float* __restrict__ out)
{
  __shared__ float tp[8][17*16];
  const int wid = threadIdx.x >> 5, l = threadIdx.x & 31, j = l & 15;
  const int p = blockIdx.x*8 + wid;
  const unsigned FULL = 0xffffffffu;

  float R[16];
  {
    const float4* Vp = (const float4*)(g_V + p*256 + j*16);
    #pragma unroll
    for (int q=0; q<4; ++q){ float4 t = Vp[q];
      R[q*4]=t.x; R[q*4+1]=t.y; R[q*4+2]=t.z; R[q*4+3]=t.w; }
  }
  float gph[16], n2 = 0.f;
  #pragma unroll
  for (int i=0;i<16;++i){ float d = g_y[p*16+i]-g_ys[p*16+i]; gph[i]=d; n2+=d*d; }
  float inv = 1.f/(sqrtf(n2)+1e-8f);
  #pragma unroll
  for (int i=0;i<16;++i) gph[i]*=inv;
  float gx = 0.f;
  #pragma unroll
  for (int i=0;i<16;++i) gx += R[i]*gph[i];

  float A[16];
  #pragma unroll
  for (int k=0;k<16;++k){
    float s = 0.f;
    #pragma unroll
    for (int i=0;i<16;++i) s += R[i]*__shfl_sync(FULL, R[i], k);
    A[k] = s + ((k==j)?1e-6f:0.f);
  }

  #pragma unroll
  for (int k=0;k<16;++k){
    float akk = __shfl_sync(FULL, A[k], k);
    float dk  = sqrtf(fmaxf(akk, 1e-30f));
    float idk = 1.f/dk;
    float cand = A[k]*idk;
    A[k] = (j>=k)? cand : A[k];
    float mylk = (j>k)? A[k] : 0.f;
    #pragma unroll
    for (int i=k+1;i<16;++i){
      float lik = __shfl_sync(FULL, A[k], i);
      A[i] -= mylk*lik;
    }
  }

  float acc = 0.f, yvj = 0.f;
  #pragma unroll
  for (int i=0;i<16;++i){
    float num = __shfl_sync(FULL, gx - acc, i);
    float di  = __shfl_sync(FULL, A[i], i);
    float yvi = num/di;
    if (j==i) yvj = yvi;
    acc += ((j>i)? A[i] : 0.f)*yvi;
  }

  if (l < 16){
    #pragma unroll
    for (int i=0;i<16;++i) tp[wid][j*17 + i] = A[i];
  }
  __syncwarp();
  float U[16];
  #pragma unroll
  for (int i=0;i<16;++i) U[i] = tp[wid][i*17 + j];

  float acc2 = 0.f, sj = 0.f;
  #pragma unroll
  for (int i=15;i>=0;--i){
    float num = __shfl_sync(FULL, yvj - acc2, i);
    float di  = __shfl_sync(FULL, U[i], i);
    float si  = num/di;
    if (j==i) sj = si;
    acc2 += ((j<i)? U[i] : 0.f)*si;
  }
  if (l < 16) out[p*16 + j] = -sj;
}

extern "C" void kernel_launch(void* const* d_in, const int* in_sizes, int n_in,
                              void* d_out, int out_size)
{
  const float* x  = (const float*)d_in[0];
  const float* xs = (const float*)d_in[1];
  const float* W0 = (const float*)d_in[2];
  const float* b0 = (const float*)d_in[3];
  const float* W1 = (const float*)d_in[4];
  const float* b1 = (const float*)d_in[5];
  const float* W2 = (const float*)d_in[6];
  const float* b2 = (const float*)d_in[7];
  const float* W3 = (const float*)d_in[8];
  const float* b3 = (const float*)d_in[9];
  const float* W4 = (const float*)d_in[10];
  const float* b4 = (const float*)d_in[11];
  float* out = (float*)d_out;

  prep<<<204,256>>>(W0,W1,W2,W3,W4);
  cudaFuncSetAttribute(flow, cudaFuncAttributeMaxDynamicSharedMemorySize, S_TOT);
  flow<<<147,256,S_TOT>>>(x,xs,b0,b1,b2,b3,b4);
  finalize2<<<128,256>>>(out);
}